// round 7
// baseline (speedup 1.0000x reference)
#include <cuda_runtime.h>
#include <math.h>

#define BATCH 4
#define RAYS  4096
#define NCH   32
#define HRES  256
#define SC    48
#define NI    48
#define NALL  96

// Transposed planes: (B,3,H,W,C) so channels are contiguous (coalesced taps).
__device__ float g_planesT[(size_t)BATCH * 3 * HRES * HRES * NCH];
// Per-sample rgb scratch: [ray][sample][channel]
__device__ float g_rgb[(size_t)BATCH * RAYS * NALL * NCH];

// Decode-MLP weights in constant memory (lane-uniform reads -> const port, not L1)
__constant__ float2 c_w1p[32 * 32];   // [c][u] = (w1[c][2u], w1[c][2u+1])
__constant__ float2 c_w2pT[17 * 64];  // [rp][j] = (w2[j][2rp], w2[j][2rp+1]); rp=16 pads .y=0
__constant__ float  c_b1[64];
__constant__ float  c_b2[33];
__constant__ float  c_bw1[67 * 64];
__constant__ float  c_bb1[64];
__constant__ float  c_bw2[64 * 32];
__constant__ float  c_bb2[32];

__device__ __forceinline__ float softplusf_fast(float x) {
    return fmaxf(x, 0.0f) + __logf(1.0f + __expf(-fabsf(x)));
}
__device__ __forceinline__ float sigmoidf_fast(float x) {
    return 1.0f / (1.0f + __expf(-x));
}
__device__ __forceinline__ float2 ffma2(float2 a, float2 b, float2 c) {
    unsigned long long ra = *reinterpret_cast<unsigned long long*>(&a);
    unsigned long long rb = *reinterpret_cast<unsigned long long*>(&b);
    unsigned long long rc = *reinterpret_cast<unsigned long long*>(&c);
    unsigned long long rd;
    asm("fma.rn.f32x2 %0, %1, %2, %3;" : "=l"(rd) : "l"(ra), "l"(rb), "l"(rc));
    return *reinterpret_cast<float2*>(&rd);
}

// ---------------------------------------------------------------------------
// Transpose (B,3,C,H,W) -> (B,3,H,W,C)
// ---------------------------------------------------------------------------
__global__ void transpose_planes_kernel(const float* __restrict__ planes) {
    __shared__ float tile[32][33];
    const int bp  = blockIdx.y;              // 0..11
    const int hw0 = blockIdx.x * 32;
    const float* src = planes + (size_t)bp * NCH * HRES * HRES;
    #pragma unroll
    for (int c = threadIdx.y; c < 32; c += 8)
        tile[c][threadIdx.x] = src[(size_t)c * (HRES * HRES) + hw0 + threadIdx.x];
    __syncthreads();
    float* dst = g_planesT + (size_t)bp * HRES * HRES * NCH;
    #pragma unroll
    for (int r = threadIdx.y; r < 32; r += 8)
        dst[(size_t)(hw0 + r) * NCH + threadIdx.x] = tile[threadIdx.x][r];
}

// ---------------------------------------------------------------------------
// Mega-kernel: one WARP per ray. MLP with lane=sample, weights via const pipe.
// ---------------------------------------------------------------------------
__global__ __launch_bounds__(32) void render_kernel(
    const float* __restrict__ ro, const float* __restrict__ rd,
    const float* __restrict__ zbg, float* __restrict__ out)
{
    const int lane = threadIdx.x;
    const int ray  = blockIdx.x;
    const int b    = ray >> 12;

    __shared__ float sstage[32 * 33];  // feature tile, then rgb staging
    __shared__ float zall[NALL];       // [0..47] coarse, [48..95] fine
    __shared__ float sig_s[NALL];
    __shared__ float cdf[46];
    __shared__ float wcl[47];
    __shared__ unsigned char perm[NALL];
    __shared__ float wall[NALL - 1];
    __shared__ float alpha_s[NALL - 1];
    __shared__ float bgh[64];
    __shared__ float sca[3];           // T, wt, dacc

    const float STEP = (3.3f - 2.25f) / 47.0f;

    const float ox = __ldg(ro + ray * 3 + 0);
    const float oy = __ldg(ro + ray * 3 + 1);
    const float oz = __ldg(ro + ray * 3 + 2);
    const float dx = __ldg(rd + ray * 3 + 0);
    const float dy = __ldg(rd + ray * 3 + 1);
    const float dz = __ldg(rd + ray * 3 + 2);

    for (int i = lane; i < SC; i += 32)
        zall[i] = 2.25f + ((float)i + 0.5f) * STEP;

    // --- background MLP (67 -> 64 -> 32), weights from const ---
    float ba0 = c_bb1[lane], ba1 = c_bb1[lane + 32];
    ba0 = fmaf(dx, c_bw1[0 * 64 + lane], ba0); ba1 = fmaf(dx, c_bw1[0 * 64 + 32 + lane], ba1);
    ba0 = fmaf(dy, c_bw1[1 * 64 + lane], ba0); ba1 = fmaf(dy, c_bw1[1 * 64 + 32 + lane], ba1);
    ba0 = fmaf(dz, c_bw1[2 * 64 + lane], ba0); ba1 = fmaf(dz, c_bw1[2 * 64 + 32 + lane], ba1);
    {
        const float* zb = zbg + b * 64;
        #pragma unroll 4
        for (int i = 0; i < 64; i++) {
            const float x = __ldg(zb + i);
            ba0 = fmaf(x, c_bw1[(3 + i) * 64 + lane],      ba0);
            ba1 = fmaf(x, c_bw1[(3 + i) * 64 + 32 + lane], ba1);
        }
    }
    bgh[lane]      = softplusf_fast(ba0);
    bgh[lane + 32] = softplusf_fast(ba1);
    __syncwarp();
    float bacc = c_bb2[lane];
    #pragma unroll 8
    for (int h = 0; h < 64; h++)
        bacc = fmaf(bgh[h], c_bw2[h * 32 + lane], bacc);
    const float bgc_r = sigmoidf_fast(bacc);   // lives in a register (lane=channel)
    __syncwarp();

    const float* pb = g_planesT + (size_t)(b * 3) * (HRES * HRES * NCH) + lane;

    // ---- one pass: gather + decode 24 samples (zall[sbase..sbase+23]) ----
    auto sample24 = [&](int sbase) {
        const float myt = zall[sbase + ((lane < 24) ? lane : 0)];
        #pragma unroll 2
        for (int s = 0; s < 24; s++) {
            const float t = __shfl_sync(0xffffffffu, myt, s);
            const float cxx = 2.0f * fmaf(t, dx, ox);
            const float cyy = 2.0f * fmaf(t, dy, oy);
            const float czz = 2.0f * fmaf(t, dz, oz);
            float feat = 0.0f;
            #pragma unroll
            for (int p = 0; p < 3; p++) {
                const float gx = (p == 2) ? czz : cxx;
                const float gy = (p == 0) ? cyy : ((p == 1) ? czz : cxx);
                const float x = fmaf(gx + 1.0f, 128.0f, -0.5f);
                const float y = fmaf(gy + 1.0f, 128.0f, -0.5f);
                const float x0f = floorf(x), y0f = floorf(y);
                const float wx = x - x0f, wy = y - y0f;
                const int x0 = (int)x0f, y0 = (int)y0f;
                const float* base = pb + (size_t)p * (HRES * HRES * NCH);
                auto tap = [&](int xi, int yi, float w) -> float {
                    const bool v = ((unsigned)xi < 256u) && ((unsigned)yi < 256u);
                    const int xcl = min(max(xi, 0), 255);
                    const int ycl = min(max(yi, 0), 255);
                    const float val = __ldg(base + (((ycl << 8) + xcl) << 5));
                    return v ? val * w : 0.0f;
                };
                feat += tap(x0,     y0,     (1.0f - wx) * (1.0f - wy));
                feat += tap(x0 + 1, y0,     wx * (1.0f - wy));
                feat += tap(x0,     y0 + 1, (1.0f - wx) * wy);
                feat += tap(x0 + 1, y0 + 1, wx * wy);
            }
            sstage[s * 33 + lane] = feat * (1.0f / 3.0f);
        }
        __syncwarp();

        // --- MLP: lane = sample; weights lane-uniform from __constant__ ---
        float2 o[17];
        #pragma unroll
        for (int rp = 0; rp < 16; rp++)
            o[rp] = make_float2(c_b2[2 * rp], c_b2[2 * rp + 1]);
        o[16] = make_float2(c_b2[32], 0.0f);

        #pragma unroll 1
        for (int chunk = 0; chunk < 4; chunk++) {
            float2 acc[8];
            #pragma unroll
            for (int q = 0; q < 8; q++) {
                const int u = chunk * 8 + q;
                acc[q] = make_float2(c_b1[2 * u], c_b1[2 * u + 1]);
            }
            #pragma unroll 8
            for (int c = 0; c < 32; c++) {
                const float fc = sstage[lane * 33 + c];   // stride-33, conflict-free
                const float2 fcc = make_float2(fc, fc);
                #pragma unroll
                for (int q = 0; q < 8; q++)
                    acc[q] = ffma2(fcc, c_w1p[c * 32 + chunk * 8 + q], acc[q]);
            }
            #pragma unroll 2
            for (int q = 0; q < 8; q++) {
                const int j0 = chunk * 16 + 2 * q;
                const float h0 = softplusf_fast(acc[q].x);
                const float h1 = softplusf_fast(acc[q].y);
                const float2 h00 = make_float2(h0, h0);
                const float2 h11 = make_float2(h1, h1);
                #pragma unroll
                for (int rp = 0; rp < 17; rp++) {
                    o[rp] = ffma2(h00, c_w2pT[rp * 64 + j0],     o[rp]);
                    o[rp] = ffma2(h11, c_w2pT[rp * 64 + j0 + 1], o[rp]);
                }
            }
        }
        __syncwarp();   // sstage feature reads complete before overwrite

        if (lane < 24) sig_s[sbase + lane] = o[0].x;   // raw sigma (out 0)
        #pragma unroll
        for (int m = 1; m <= 32; m++) {
            const float v = (m & 1) ? o[m >> 1].y : o[m >> 1].x;
            sstage[lane * 33 + (m - 1)] = sigmoidf_fast(v) * 1.002f - 0.001f;
        }
        __syncwarp();
        float* grow = g_rgb + ((size_t)ray * NALL + sbase) * NCH;
        #pragma unroll 4
        for (int s = 0; s < 24; s++)
            grow[s * NCH + lane] = sstage[s * 33 + lane];   // coalesced
        __syncwarp();
    };

    // --- Phase A: coarse ---
    sample24(0);
    sample24(24);

    for (int i = lane; i < 47; i += 32) {
        const float dens = softplusf_fast(0.5f * (sig_s[i] + sig_s[i + 1]) - 1.0f);
        alpha_s[i] = 1.0f - __expf(-dens * STEP);
    }
    __syncwarp();

    if (lane == 0) {
        float T = 1.0f;
        #pragma unroll 4
        for (int i = 0; i < 47; i++) {
            const float a = alpha_s[i];
            wcl[i] = a * T;
            T *= (1.0f - a + 1e-10f);
        }
        float s = 0.0f;
        #pragma unroll 4
        for (int k = 0; k < 45; k++) {
            const float a  = fmaxf(wcl[k],     wcl[k + 1]) + 0.01f;
            const float bb = fmaxf(wcl[k + 1], wcl[k + 2]) + 0.01f;
            const float v  = 0.5f * (a + bb) + 0.01f + 1e-5f;
            wall[k] = v;  // scratch
            s += v;
        }
        const float inv = 1.0f / s;
        cdf[0] = 0.0f;
        float acc = 0.0f;
        #pragma unroll 4
        for (int k = 0; k < 45; k++) { acc += wall[k] * inv; cdf[k + 1] = acc; }
    }
    __syncwarp();

    // inverse-CDF: 48 sorted fine depths -> zall[48..95]
    for (int i = lane; i < NI; i += 32) {
        const float u = ((float)i + 0.5f) * (1.0f / 48.0f);
        int idx = 0;
        while (idx < 46 && cdf[idx] <= u) idx++;
        int below = idx - 1; if (below < 0) below = 0; if (below > 45) below = 45;
        int above = idx;     if (above > 45) above = 45;
        const float cb = cdf[below], ca = cdf[above];
        float den = ca - cb; if (den < 1e-5f) den = 1.0f;
        const float bbv = 2.25f + ((float)below + 1.0f) * STEP;   // zmid closed form
        const float bav = 2.25f + ((float)above + 1.0f) * STEP;
        zall[SC + i] = fmaf((u - cb) / den, bav - bbv, bbv);
    }
    __syncwarp();

    // --- Phase D: fine ---
    sample24(48);
    sample24(72);

    // --- stable merge by rank-counting (coarse first on ties) ---
    for (int i = lane; i < SC; i += 32) {
        const float zv = zall[i];
        int c = 0;
        #pragma unroll 8
        for (int k = 0; k < NI; k++) c += (zall[SC + k] < zv) ? 1 : 0;
        perm[i + c] = (unsigned char)i;
    }
    for (int j = lane; j < NI; j += 32) {
        const float zv = zall[SC + j];
        int c = 0;
        #pragma unroll 8
        for (int k = 0; k < SC; k++) c += (zall[k] <= zv) ? 1 : 0;
        perm[j + c] = (unsigned char)(SC + j);
    }
    __syncwarp();

    // final-march alphas (parallel)
    for (int k = lane; k < NALL - 1; k += 32) {
        const float delta = zall[perm[k + 1]] - zall[perm[k]];
        const float dens  = softplusf_fast(0.5f * (sig_s[perm[k]] + sig_s[perm[k + 1]]) - 1.0f);
        alpha_s[k] = 1.0f - __expf(-dens * delta);
    }
    __syncwarp();

    if (lane == 0) {
        float T = 1.0f, wt = 0.0f, dacc = 0.0f;
        float dprev = zall[perm[0]];
        #pragma unroll 4
        for (int k = 0; k < NALL - 1; k++) {
            const float dnext = zall[perm[k + 1]];
            const float a = alpha_s[k];
            const float w = a * T;
            wall[k] = w;
            wt += w;
            dacc = fmaf(w, 0.5f * (dprev + dnext), dacc);
            T *= (1.0f - a + 1e-10f);
            dprev = dnext;
        }
        sca[0] = T; sca[1] = wt; sca[2] = dacc;
    }
    __syncwarp();

    // --- composite (lane = channel; coalesced rows from g_rgb) ---
    const size_t rbase = (size_t)ray * NALL * NCH;
    float rprev = g_rgb[rbase + (size_t)perm[0] * NCH + lane];
    float acc = 0.0f;
    #pragma unroll 1
    for (int k = 0; k < NALL - 1; k++) {
        const float rnext = g_rgb[rbase + (size_t)perm[k + 1] * NCH + lane];
        acc = fmaf(wall[k], 0.5f * (rprev + rnext), acc);
        rprev = rnext;
    }
    acc = fmaf(sca[0], bgc_r, acc);

    float* out_rgb   = out;
    float* out_depth = out + (size_t)BATCH * RAYS * 32;
    float* out_wsum  = out + (size_t)BATCH * RAYS * 33;

    out_rgb[(size_t)ray * 32 + lane] = acc * 2.0f - 1.0f;
    if (lane == 0) {
        float dv = sca[2] / sca[1];
        if (dv != dv) dv = INFINITY;
        const float ZMIN = 2.25f + 0.5f  * STEP;
        const float ZMAX = 2.25f + 47.5f * STEP;
        dv = fminf(fmaxf(dv, ZMIN), ZMAX);
        out_depth[ray] = dv;
        out_wsum[ray]  = sca[1];
    }
}

// ---------------------------------------------------------------------------
extern "C" void kernel_launch(void* const* d_in, const int* in_sizes, int n_in,
                              void* d_out, int out_size) {
    const float* planes = (const float*)d_in[0];
    const float* ro     = (const float*)d_in[1];
    const float* rd     = (const float*)d_in[2];
    const float* zbg    = (const float*)d_in[3];
    const float* w1     = (const float*)d_in[4];
    const float* b1     = (const float*)d_in[5];
    const float* w2     = (const float*)d_in[6];
    const float* b2     = (const float*)d_in[7];
    const float* bw1    = (const float*)d_in[8];
    const float* bb1    = (const float*)d_in[9];
    const float* bw2    = (const float*)d_in[10];
    const float* bb2    = (const float*)d_in[11];
    float* out = (float*)d_out;

    // Populate constant memory (all async D2D; graph-capturable memcpy nodes).
    cudaMemcpyToSymbolAsync(c_w1p, w1, 32 * 64 * sizeof(float), 0,
                            cudaMemcpyDeviceToDevice, 0);
    cudaMemcpyToSymbolAsync(c_b1,  b1, 64 * sizeof(float), 0,
                            cudaMemcpyDeviceToDevice, 0);
    cudaMemcpyToSymbolAsync(c_b2,  b2, 33 * sizeof(float), 0,
                            cudaMemcpyDeviceToDevice, 0);
    cudaMemcpyToSymbolAsync(c_bw1, bw1, 67 * 64 * sizeof(float), 0,
                            cudaMemcpyDeviceToDevice, 0);
    cudaMemcpyToSymbolAsync(c_bb1, bb1, 64 * sizeof(float), 0,
                            cudaMemcpyDeviceToDevice, 0);
    cudaMemcpyToSymbolAsync(c_bw2, bw2, 64 * 32 * sizeof(float), 0,
                            cudaMemcpyDeviceToDevice, 0);
    cudaMemcpyToSymbolAsync(c_bb2, bb2, 32 * sizeof(float), 0,
                            cudaMemcpyDeviceToDevice, 0);
    // c_w2pT[rp][j] = (w2[j][2rp], w2[j][2rp+1]) via strided 2D copies.
    void* w2pT_dev = nullptr;
    cudaGetSymbolAddress(&w2pT_dev, c_w2pT);
    for (int rp = 0; rp < 17; rp++) {
        const size_t width = (rp == 16) ? 4 : 8;     // rp=16: only w2[j][32]; pad .y stays 0
        cudaMemcpy2DAsync((char*)w2pT_dev + (size_t)rp * 64 * 8, 8,
                          (const char*)w2 + (size_t)rp * 8, 33 * 4,
                          width, 64, cudaMemcpyDeviceToDevice, 0);
    }

    dim3 tgrid(HRES * HRES / 32, BATCH * 3);
    transpose_planes_kernel<<<tgrid, dim3(32, 8)>>>(planes);
    render_kernel<<<BATCH * RAYS, 32>>>(ro, rd, zbg, out);
}

// round 8
// speedup vs baseline: 9.0504x; 9.0504x over previous
#include <cuda_runtime.h>
#include <math.h>

#define BATCH 4
#define RAYS  4096
#define NR    (BATCH * RAYS)
#define NCH   32
#define HRES  256
#define SC    48
#define NI    48
#define NALL  96
#define STEPF ((3.3f - 2.25f) / 47.0f)

// Transposed planes: (B,3,H,W,C) so channels are contiguous (coalesced taps).
__device__ float g_planesT[(size_t)BATCH * 3 * HRES * HRES * NCH];
// Per-sample raw sigma and rgb scratch.
__device__ float g_sigma[(size_t)NR * NALL];
__device__ float g_rgbb[(size_t)NR * NALL * NCH];
__device__ float g_zfine[(size_t)NR * NI];

__device__ __forceinline__ float softplusf_fast(float x) {
    return fmaxf(x, 0.0f) + __logf(1.0f + __expf(-fabsf(x)));
}
__device__ __forceinline__ float sigmoidf_fast(float x) {
    return 1.0f / (1.0f + __expf(-x));
}
__device__ __forceinline__ float2 ffma2(float2 a, float2 b, float2 c) {
    unsigned long long ra = *reinterpret_cast<unsigned long long*>(&a);
    unsigned long long rb = *reinterpret_cast<unsigned long long*>(&b);
    unsigned long long rc = *reinterpret_cast<unsigned long long*>(&c);
    unsigned long long rd;
    asm("fma.rn.f32x2 %0, %1, %2, %3;" : "=l"(rd) : "l"(ra), "l"(rb), "l"(rc));
    return *reinterpret_cast<float2*>(&rd);
}

// ---------------------------------------------------------------------------
// Transpose (B,3,C,H,W) -> (B,3,H,W,C)
// ---------------------------------------------------------------------------
__global__ void transpose_planes_kernel(const float* __restrict__ planes) {
    __shared__ float tile[32][33];
    const int bp  = blockIdx.y;
    const int hw0 = blockIdx.x * 32;
    const float* src = planes + (size_t)bp * NCH * HRES * HRES;
    #pragma unroll
    for (int c = threadIdx.y; c < 32; c += 8)
        tile[c][threadIdx.x] = src[(size_t)c * (HRES * HRES) + hw0 + threadIdx.x];
    __syncthreads();
    float* dst = g_planesT + (size_t)bp * HRES * HRES * NCH;
    #pragma unroll
    for (int r = threadIdx.y; r < 32; r += 8)
        dst[(size_t)(hw0 + r) * NCH + threadIdx.x] = tile[threadIdx.x][r];
}

// ---------------------------------------------------------------------------
// Decode: sample-parallel warp-GEMM. 1 warp = 8 samples of one ray.
// grid = NR*6/4 blocks of 128 threads; launched twice (fine=0/1).
// ---------------------------------------------------------------------------
__global__ __launch_bounds__(128) void decode_kernel(
    const float* __restrict__ ro, const float* __restrict__ rd,
    const float* __restrict__ w1, const float* __restrict__ b1,
    const float* __restrict__ w2, const float* __restrict__ b2,
    const int fine)
{
    __shared__ float2 sw1p[32 * 32];   // [c][l] = (w1[c][2l], w1[c][2l+1])
    __shared__ float2 sw2p[32 * 32];   // [k][ch] = (w2[2k][1+ch], w2[2k+1][1+ch])
    __shared__ float2 wsig2[32];       // [l] = (w2[2l][0], w2[2l+1][0])
    __shared__ float2 sb1p[32];        // (b1[2l], b1[2l+1])
    __shared__ float  sb2r[32];        // b2[1+ch]
    __shared__ float  sb2sig;
    __shared__ __align__(16) float sstage[4][1152];  // per-warp staging (feats, then h)

    const int tid  = threadIdx.x;
    const int warp = tid >> 5;
    const int lane = tid & 31;

    // --- stage weights ---
    const float2* w1v = (const float2*)w1;   // pairs (2l,2l+1) are contiguous
    for (int i = tid; i < 1024; i += 128) sw1p[i] = w1v[i];
    for (int i = tid; i < 1024; i += 128) {
        const int k = i >> 5, ch = i & 31;
        sw2p[i] = make_float2(w2[(2 * k) * 33 + 1 + ch], w2[(2 * k + 1) * 33 + 1 + ch]);
    }
    if (tid < 32) {
        wsig2[tid] = make_float2(w2[(2 * tid) * 33], w2[(2 * tid + 1) * 33]);
        sb1p[tid]  = ((const float2*)b1)[tid];
        sb2r[tid]  = b2[1 + tid];
    }
    if (tid == 0) sb2sig = b2[0];
    __syncthreads();

    const int gw    = blockIdx.x * 4 + warp;
    const int ray   = gw / 6;
    const int sbase = (gw % 6) * 8;
    const int b     = ray >> 12;
    const int soff  = fine ? SC : 0;

    const float ox = __ldg(ro + ray * 3 + 0);
    const float oy = __ldg(ro + ray * 3 + 1);
    const float oz = __ldg(ro + ray * 3 + 2);
    const float dx = __ldg(rd + ray * 3 + 0);
    const float dy = __ldg(rd + ray * 3 + 1);
    const float dz = __ldg(rd + ray * 3 + 2);

    const float* pb = g_planesT + (size_t)(b * 3) * (HRES * HRES * NCH) + lane;
    float* stg = sstage[warp];

    // --- gather 8 samples (lane = channel, coalesced 128B taps) ---
    float ff[8];
    #pragma unroll
    for (int s = 0; s < 8; s++) {
        float t;
        if (fine) t = __ldg(&g_zfine[(size_t)ray * NI + sbase + s]);
        else      t = 2.25f + ((float)(sbase + s) + 0.5f) * STEPF;
        const float cxx = 2.0f * fmaf(t, dx, ox);
        const float cyy = 2.0f * fmaf(t, dy, oy);
        const float czz = 2.0f * fmaf(t, dz, oz);
        float feat = 0.0f;
        #pragma unroll
        for (int p = 0; p < 3; p++) {
            const float gx = (p == 2) ? czz : cxx;
            const float gy = (p == 0) ? cyy : ((p == 1) ? czz : cxx);
            const float x = fmaf(gx + 1.0f, 128.0f, -0.5f);
            const float y = fmaf(gy + 1.0f, 128.0f, -0.5f);
            const float x0f = floorf(x), y0f = floorf(y);
            const float wx = x - x0f, wy = y - y0f;
            const int x0 = (int)x0f, y0 = (int)y0f;
            const float* base = pb + (size_t)p * (HRES * HRES * NCH);
            auto tap = [&](int xi, int yi, float w) -> float {
                const bool v = ((unsigned)xi < 256u) && ((unsigned)yi < 256u);
                const int xcl = min(max(xi, 0), 255);
                const int ycl = min(max(yi, 0), 255);
                const float val = __ldg(base + (((ycl << 8) + xcl) << 5));
                return v ? val * w : 0.0f;
            };
            feat += tap(x0,     y0,     (1.0f - wx) * (1.0f - wy));
            feat += tap(x0 + 1, y0,     wx * (1.0f - wy));
            feat += tap(x0,     y0 + 1, (1.0f - wx) * wy);
            feat += tap(x0 + 1, y0 + 1, wx * wy);
        }
        ff[s] = feat * (1.0f / 3.0f);
    }
    // feats layout [c][12]-stride: conflict-free STS.128, aligned float4 rows
    *(float4*)(stg + lane * 12)     = make_float4(ff[0], ff[1], ff[2], ff[3]);
    *(float4*)(stg + lane * 12 + 4) = make_float4(ff[4], ff[5], ff[6], ff[7]);
    __syncwarp();

    // --- hidden layer: lane owns units (2*lane, 2*lane+1), 8 samples ---
    float2 acc[8];
    {
        const float2 bp = sb1p[lane];
        #pragma unroll
        for (int s = 0; s < 8; s++) acc[s] = bp;
    }
    #pragma unroll 4
    for (int c = 0; c < 32; c++) {
        const float4 f03 = *(const float4*)(stg + c * 12);      // broadcast
        const float4 f47 = *(const float4*)(stg + c * 12 + 4);  // broadcast
        const float2 w = sw1p[c * 32 + lane];
        acc[0] = ffma2(make_float2(f03.x, f03.x), w, acc[0]);
        acc[1] = ffma2(make_float2(f03.y, f03.y), w, acc[1]);
        acc[2] = ffma2(make_float2(f03.z, f03.z), w, acc[2]);
        acc[3] = ffma2(make_float2(f03.w, f03.w), w, acc[3]);
        acc[4] = ffma2(make_float2(f47.x, f47.x), w, acc[4]);
        acc[5] = ffma2(make_float2(f47.y, f47.y), w, acc[5]);
        acc[6] = ffma2(make_float2(f47.z, f47.z), w, acc[6]);
        acc[7] = ffma2(make_float2(f47.w, f47.w), w, acc[7]);
    }
    float h0[8], h1[8];
    #pragma unroll
    for (int s = 0; s < 8; s++) {
        h0[s] = softplusf_fast(acc[s].x);
        h1[s] = softplusf_fast(acc[s].y);
    }

    // --- sigma: partial per lane, butterfly reduce (8 independent sums) ---
    float p[8];
    {
        const float2 ws = wsig2[lane];
        #pragma unroll
        for (int s = 0; s < 8; s++) p[s] = fmaf(h0[s], ws.x, h1[s] * ws.y);
    }
    #pragma unroll
    for (int off = 16; off; off >>= 1) {
        #pragma unroll
        for (int s = 0; s < 8; s++)
            p[s] += __shfl_xor_sync(0xffffffffu, p[s], off);
    }

    // --- stage h: row k=lane, 16 floats (pairs per sample), row stride 36 ---
    __syncwarp();
    *(float4*)(stg + lane * 36 + 0)  = make_float4(h0[0], h1[0], h0[1], h1[1]);
    *(float4*)(stg + lane * 36 + 4)  = make_float4(h0[2], h1[2], h0[3], h1[3]);
    *(float4*)(stg + lane * 36 + 8)  = make_float4(h0[4], h1[4], h0[5], h1[5]);
    *(float4*)(stg + lane * 36 + 12) = make_float4(h0[6], h1[6], h0[7], h1[7]);
    __syncwarp();

    // --- output layer: lane = rgb channel, 8 samples ---
    float2 o2[8];
    #pragma unroll
    for (int s = 0; s < 8; s++) o2[s] = make_float2(0.0f, 0.0f);
    #pragma unroll 4
    for (int k = 0; k < 32; k++) {
        const float2 w = sw2p[k * 32 + lane];
        const float4 q0 = *(const float4*)(stg + k * 36 + 0);   // (h0_0,h1_0,h0_1,h1_1)
        const float4 q1 = *(const float4*)(stg + k * 36 + 4);
        const float4 q2 = *(const float4*)(stg + k * 36 + 8);
        const float4 q3 = *(const float4*)(stg + k * 36 + 12);
        o2[0] = ffma2(make_float2(q0.x, q0.y), w, o2[0]);
        o2[1] = ffma2(make_float2(q0.z, q0.w), w, o2[1]);
        o2[2] = ffma2(make_float2(q1.x, q1.y), w, o2[2]);
        o2[3] = ffma2(make_float2(q1.z, q1.w), w, o2[3]);
        o2[4] = ffma2(make_float2(q2.x, q2.y), w, o2[4]);
        o2[5] = ffma2(make_float2(q2.z, q2.w), w, o2[5]);
        o2[6] = ffma2(make_float2(q3.x, q3.y), w, o2[6]);
        o2[7] = ffma2(make_float2(q3.z, q3.w), w, o2[7]);
    }

    // --- writeback ---
    const float bb = sb2r[lane];
    float* grow = g_rgbb + ((size_t)ray * NALL + soff + sbase) * NCH + lane;
    #pragma unroll
    for (int s = 0; s < 8; s++)
        grow[s * NCH] = sigmoidf_fast(o2[s].x + o2[s].y + bb) * 1.002f - 0.001f;

    float myp = p[0];
    if (lane == 1) myp = p[1];
    if (lane == 2) myp = p[2];
    if (lane == 3) myp = p[3];
    if (lane == 4) myp = p[4];
    if (lane == 5) myp = p[5];
    if (lane == 6) myp = p[6];
    if (lane == 7) myp = p[7];
    if (lane < 8)
        g_sigma[(size_t)ray * NALL + soff + sbase + lane] = myp + sb2sig;
}

// ---------------------------------------------------------------------------
// March: coarse weights -> smoothed pdf/cdf -> 48 fine depths. 1 warp/ray.
// ---------------------------------------------------------------------------
__global__ __launch_bounds__(128) void march_kernel() {
    __shared__ float salpha[4][47];
    __shared__ float swk[4][45];
    __shared__ float scdf[4][46];

    const int warp = threadIdx.x >> 5;
    const int lane = threadIdx.x & 31;
    const int ray  = blockIdx.x * 4 + warp;

    const float* sg = g_sigma + (size_t)ray * NALL;
    for (int i = lane; i < 47; i += 32) {
        const float dens = softplusf_fast(0.5f * (__ldg(sg + i) + __ldg(sg + i + 1)) - 1.0f);
        salpha[warp][i] = 1.0f - __expf(-dens * STEPF);
    }
    __syncwarp();

    if (lane == 0) {
        float wcl[47];
        float T = 1.0f;
        #pragma unroll 4
        for (int i = 0; i < 47; i++) {
            const float a = salpha[warp][i];
            wcl[i] = a * T;
            T *= (1.0f - a + 1e-10f);
        }
        float s = 0.0f;
        #pragma unroll 4
        for (int k = 0; k < 45; k++) {
            const float a  = fmaxf(wcl[k],     wcl[k + 1]) + 0.01f;
            const float bb = fmaxf(wcl[k + 1], wcl[k + 2]) + 0.01f;
            const float v  = 0.5f * (a + bb) + 0.01f + 1e-5f;
            swk[warp][k] = v;
            s += v;
        }
        const float inv = 1.0f / s;
        scdf[warp][0] = 0.0f;
        float acc = 0.0f;
        #pragma unroll 4
        for (int k = 0; k < 45; k++) { acc += swk[warp][k] * inv; scdf[warp][k + 1] = acc; }
    }
    __syncwarp();

    for (int i = lane; i < NI; i += 32) {
        const float u = ((float)i + 0.5f) * (1.0f / 48.0f);
        int idx = 0;
        while (idx < 46 && scdf[warp][idx] <= u) idx++;
        int below = idx - 1; if (below < 0) below = 0; if (below > 45) below = 45;
        int above = idx;     if (above > 45) above = 45;
        const float cb = scdf[warp][below], ca = scdf[warp][above];
        float den = ca - cb; if (den < 1e-5f) den = 1.0f;
        const float bbv = 2.25f + ((float)below + 1.0f) * STEPF;  // zmid closed form
        const float bav = 2.25f + ((float)above + 1.0f) * STEPF;
        g_zfine[(size_t)ray * NI + i] = fmaf((u - cb) / den, bav - bbv, bbv);
    }
}

// ---------------------------------------------------------------------------
// Final: merge, march, bg MLP, composite. 1 warp/ray.
// ---------------------------------------------------------------------------
__global__ __launch_bounds__(128) void final_kernel(
    const float* __restrict__ rd, const float* __restrict__ zbg,
    const float* __restrict__ bw1, const float* __restrict__ bb1,
    const float* __restrict__ bw2, const float* __restrict__ bb2,
    float* __restrict__ out)
{
    __shared__ float zall[4][NALL];
    __shared__ float sig[4][NALL];
    __shared__ unsigned char perm[4][NALL];
    __shared__ float alpha_s[4][NALL - 1];
    __shared__ float wall[4][NALL - 1];
    __shared__ float bgh[4][64];
    __shared__ float sca[4][3];

    const int warp = threadIdx.x >> 5;
    const int lane = threadIdx.x & 31;
    const int ray  = blockIdx.x * 4 + warp;
    const int b    = ray >> 12;

    const float dx = __ldg(rd + ray * 3 + 0);
    const float dy = __ldg(rd + ray * 3 + 1);
    const float dz = __ldg(rd + ray * 3 + 2);

    // load sigma + depths
    for (int i = lane; i < NALL; i += 32) {
        sig[warp][i] = __ldg(&g_sigma[(size_t)ray * NALL + i]);
        zall[warp][i] = (i < SC) ? (2.25f + ((float)i + 0.5f) * STEPF)
                                 : __ldg(&g_zfine[(size_t)ray * NI + i - SC]);
    }

    // --- background MLP (67 -> 64 -> 32), weights streamed from L2 ---
    {
        float a0 = __ldg(bb1 + lane), a1 = __ldg(bb1 + lane + 32);
        a0 = fmaf(dx, __ldg(bw1 + 0 * 64 + lane), a0);
        a1 = fmaf(dx, __ldg(bw1 + 0 * 64 + 32 + lane), a1);
        a0 = fmaf(dy, __ldg(bw1 + 1 * 64 + lane), a0);
        a1 = fmaf(dy, __ldg(bw1 + 1 * 64 + 32 + lane), a1);
        a0 = fmaf(dz, __ldg(bw1 + 2 * 64 + lane), a0);
        a1 = fmaf(dz, __ldg(bw1 + 2 * 64 + 32 + lane), a1);
        const float* zb = zbg + b * 64;
        #pragma unroll 4
        for (int i = 0; i < 64; i++) {
            const float x = __ldg(zb + i);
            a0 = fmaf(x, __ldg(bw1 + (3 + i) * 64 + lane), a0);
            a1 = fmaf(x, __ldg(bw1 + (3 + i) * 64 + 32 + lane), a1);
        }
        bgh[warp][lane]      = softplusf_fast(a0);
        bgh[warp][lane + 32] = softplusf_fast(a1);
    }
    __syncwarp();
    float bgc_r = __ldg(bb2 + lane);
    #pragma unroll 8
    for (int h = 0; h < 64; h++)
        bgc_r = fmaf(bgh[warp][h], __ldg(bw2 + h * 32 + lane), bgc_r);
    bgc_r = sigmoidf_fast(bgc_r);
    __syncwarp();

    // --- stable merge by rank-counting (coarse first on ties) ---
    for (int i = lane; i < SC; i += 32) {
        const float zv = zall[warp][i];
        int c = 0;
        #pragma unroll 8
        for (int k = 0; k < NI; k++) c += (zall[warp][SC + k] < zv) ? 1 : 0;
        perm[warp][i + c] = (unsigned char)i;
    }
    for (int j = lane; j < NI; j += 32) {
        const float zv = zall[warp][SC + j];
        int c = 0;
        #pragma unroll 8
        for (int k = 0; k < SC; k++) c += (zall[warp][k] <= zv) ? 1 : 0;
        perm[warp][j + c] = (unsigned char)(SC + j);
    }
    __syncwarp();

    // --- final-march alphas (parallel) ---
    for (int k = lane; k < NALL - 1; k += 32) {
        const float delta = zall[warp][perm[warp][k + 1]] - zall[warp][perm[warp][k]];
        const float dens  = softplusf_fast(0.5f * (sig[warp][perm[warp][k]] +
                                                   sig[warp][perm[warp][k + 1]]) - 1.0f);
        alpha_s[warp][k] = 1.0f - __expf(-dens * delta);
    }
    __syncwarp();

    if (lane == 0) {
        float T = 1.0f, wt = 0.0f, dacc = 0.0f;
        float dprev = zall[warp][perm[warp][0]];
        #pragma unroll 4
        for (int k = 0; k < NALL - 1; k++) {
            const float dnext = zall[warp][perm[warp][k + 1]];
            const float a = alpha_s[warp][k];
            const float w = a * T;
            wall[warp][k] = w;
            wt += w;
            dacc = fmaf(w, 0.5f * (dprev + dnext), dacc);
            T *= (1.0f - a + 1e-10f);
            dprev = dnext;
        }
        sca[warp][0] = T; sca[warp][1] = wt; sca[warp][2] = dacc;
    }
    __syncwarp();

    // --- composite (lane = channel; coalesced 128B rows) ---
    const size_t rbase = (size_t)ray * NALL * NCH + lane;
    float rprev = __ldg(&g_rgbb[rbase + (size_t)perm[warp][0] * NCH]);
    float acc = 0.0f;
    #pragma unroll 5
    for (int k = 0; k < NALL - 1; k++) {
        const float rnext = __ldg(&g_rgbb[rbase + (size_t)perm[warp][k + 1] * NCH]);
        acc = fmaf(wall[warp][k], 0.5f * (rprev + rnext), acc);
        rprev = rnext;
    }
    acc = fmaf(sca[warp][0], bgc_r, acc);

    float* out_rgb   = out;
    float* out_depth = out + (size_t)NR * 32;
    float* out_wsum  = out + (size_t)NR * 33;

    out_rgb[(size_t)ray * 32 + lane] = acc * 2.0f - 1.0f;
    if (lane == 0) {
        float dv = sca[warp][2] / sca[warp][1];
        if (dv != dv) dv = INFINITY;
        const float ZMIN = 2.25f + 0.5f  * STEPF;
        const float ZMAX = 2.25f + 47.5f * STEPF;
        dv = fminf(fmaxf(dv, ZMIN), ZMAX);
        out_depth[ray] = dv;
        out_wsum[ray]  = sca[warp][1];
    }
}

// ---------------------------------------------------------------------------
extern "C" void kernel_launch(void* const* d_in, const int* in_sizes, int n_in,
                              void* d_out, int out_size) {
    const float* planes = (const float*)d_in[0];
    const float* ro     = (const float*)d_in[1];
    const float* rd     = (const float*)d_in[2];
    const float* zbg    = (const float*)d_in[3];
    const float* w1     = (const float*)d_in[4];
    const float* b1     = (const float*)d_in[5];
    const float* w2     = (const float*)d_in[6];
    const float* b2     = (const float*)d_in[7];
    const float* bw1    = (const float*)d_in[8];
    const float* bb1    = (const float*)d_in[9];
    const float* bw2    = (const float*)d_in[10];
    const float* bb2    = (const float*)d_in[11];
    float* out = (float*)d_out;

    dim3 tgrid(HRES * HRES / 32, BATCH * 3);
    transpose_planes_kernel<<<tgrid, dim3(32, 8)>>>(planes);

    const int decode_blocks = NR * 6 / 4;   // 6 warp-chunks per ray, 4 warps/block
    decode_kernel<<<decode_blocks, 128>>>(ro, rd, w1, b1, w2, b2, 0);
    march_kernel<<<NR / 4, 128>>>();
    decode_kernel<<<decode_blocks, 128>>>(ro, rd, w1, b1, w2, b2, 1);
    final_kernel<<<NR / 4, 128>>>(rd, zbg, bw1, bb1, bw2, bb2, out);
}

// round 9
// speedup vs baseline: 10.8577x; 1.1997x over previous
#include <cuda_runtime.h>
#include <math.h>

#define BATCH 4
#define RAYS  4096
#define NR    (BATCH * RAYS)
#define NCH   32
#define HRES  256
#define HPAD  258
#define PLSZ  (HPAD * HPAD * NCH)
#define SC    48
#define NI    48
#define NALL  96
#define STEPF ((3.3f - 2.25f) / 47.0f)

// Bordered transposed planes: (B,3,258,258,C); 1-px border stays zero
// (device globals are zero-initialized; border cells are never written).
__device__ float g_planesT[(size_t)BATCH * 3 * PLSZ];
__device__ float g_sigma[(size_t)NR * NALL];
__device__ float g_rgbb[(size_t)NR * NALL * NCH];
__device__ float g_zfine[(size_t)NR * NI];
// Packed decode weights: [0..511] f4 = w2p pairs, [512..527] f4 = wsig2,
// [528..543] f4 = b1 pairs, floats 2176..2207 = b2[1..32], 2208 = b2[0].
__device__ float4 g_wpack[560];

__device__ __forceinline__ float softplusf_fast(float x) {
    return fmaxf(x, 0.0f) + __logf(1.0f + __expf(-fabsf(x)));
}
__device__ __forceinline__ float sigmoidf_fast(float x) {
    return 1.0f / (1.0f + __expf(-x));
}
__device__ __forceinline__ float2 ffma2(float2 a, float2 b, float2 c) {
    unsigned long long ra = *reinterpret_cast<unsigned long long*>(&a);
    unsigned long long rb = *reinterpret_cast<unsigned long long*>(&b);
    unsigned long long rc = *reinterpret_cast<unsigned long long*>(&c);
    unsigned long long rd;
    asm("fma.rn.f32x2 %0, %1, %2, %3;" : "=l"(rd) : "l"(ra), "l"(rb), "l"(rc));
    return *reinterpret_cast<float2*>(&rd);
}

// ---------------------------------------------------------------------------
// Pack decode weights once (contiguous staging for decode blocks).
// ---------------------------------------------------------------------------
__global__ void pack_weights_kernel(const float* __restrict__ w1,
                                    const float* __restrict__ b1,
                                    const float* __restrict__ w2,
                                    const float* __restrict__ b2) {
    const int tid = threadIdx.x;
    float2* wp2 = (float2*)g_wpack;
    float*  wpf = (float*)g_wpack;
    for (int i = tid; i < 1024; i += 128) {            // w2 rgb pairs
        const int k = i >> 5, ch = i & 31;
        wp2[i] = make_float2(w2[(2 * k) * 33 + 1 + ch], w2[(2 * k + 1) * 33 + 1 + ch]);
    }
    if (tid < 32) {
        wp2[1024 + tid] = make_float2(w2[(2 * tid) * 33], w2[(2 * tid + 1) * 33]); // wsig
        wp2[1056 + tid] = ((const float2*)b1)[tid];                                // b1 pairs
        wpf[2176 + tid] = b2[1 + tid];                                             // b2 rgb
    }
    if (tid == 0) wpf[2208] = b2[0];
    (void)w1;
}

// ---------------------------------------------------------------------------
// Transpose (B,3,C,256,256) -> bordered (B,3,258,258,C)
// ---------------------------------------------------------------------------
__global__ void transpose_planes_kernel(const float* __restrict__ planes) {
    __shared__ float tile[32][33];
    const int bp  = blockIdx.y;
    const int hw0 = blockIdx.x * 32;
    const float* src = planes + (size_t)bp * NCH * HRES * HRES;
    #pragma unroll
    for (int c = threadIdx.y; c < 32; c += 8)
        tile[c][threadIdx.x] = src[(size_t)c * (HRES * HRES) + hw0 + threadIdx.x];
    __syncthreads();
    float* dst = g_planesT + (size_t)bp * PLSZ;
    #pragma unroll
    for (int r = threadIdx.y; r < 32; r += 8) {
        const int hw = hw0 + r;
        const int y = hw >> 8, x = hw & 255;
        dst[(size_t)((y + 1) * HPAD + (x + 1)) * NCH + threadIdx.x] = tile[threadIdx.x][r];
    }
}

// ---------------------------------------------------------------------------
// Decode: sample-parallel warp-GEMM. 1 warp = 8 samples of one ray.
// ---------------------------------------------------------------------------
__global__ __launch_bounds__(128, 6) void decode_kernel(
    const float* __restrict__ ro, const float* __restrict__ rd,
    const float* __restrict__ w1, const int fine)
{
    __shared__ __align__(16) float2 sw1p[32 * 32]; // [c][l]=(w1[c][2l],w1[c][2l+1])
    __shared__ __align__(16) float2 sw2p[32 * 32]; // [k][ch]
    __shared__ __align__(16) float2 wsig2[32];
    __shared__ __align__(16) float2 sb1p[32];
    __shared__ float  sb2r[32];
    __shared__ float  sb2sig;
    __shared__ __align__(16) float sstage[4][1152];

    const int tid  = threadIdx.x;
    const int warp = tid >> 5;
    const int lane = tid & 31;

    // --- stage weights: pure contiguous float4 copies ---
    {
        const float4* w1v4 = (const float4*)w1;
        float4* d1 = (float4*)sw1p;
        #pragma unroll
        for (int i = tid; i < 512; i += 128) d1[i] = w1v4[i];
        float4* d2 = (float4*)sw2p;
        #pragma unroll
        for (int i = tid; i < 512; i += 128) d2[i] = g_wpack[i];
        if (tid < 16) {
            ((float4*)wsig2)[tid] = g_wpack[512 + tid];
            ((float4*)sb1p)[tid]  = g_wpack[528 + tid];
        }
        const float* wpf = (const float*)g_wpack;
        if (tid < 32) sb2r[tid] = wpf[2176 + tid];
        if (tid == 0) sb2sig = wpf[2208];
    }
    __syncthreads();

    const int gw    = blockIdx.x * 4 + warp;
    const int ray   = gw / 6;
    const int sbase = (gw % 6) * 8;
    const int b     = ray >> 12;
    const int soff  = fine ? SC : 0;

    const float ox = __ldg(ro + ray * 3 + 0);
    const float oy = __ldg(ro + ray * 3 + 1);
    const float oz = __ldg(ro + ray * 3 + 2);
    const float dx = __ldg(rd + ray * 3 + 0);
    const float dy = __ldg(rd + ray * 3 + 1);
    const float dz = __ldg(rd + ray * 3 + 2);

    // base points at interior cell (0,0) of this batch's plane 0, this lane's ch
    const float* pb = g_planesT + (size_t)(b * 3) * PLSZ + (HPAD + 1) * NCH + lane;
    float* stg = sstage[warp];

    // --- gather 8 samples (lane = channel; borderized taps, no predicates) ---
    float ff[8];
    #pragma unroll
    for (int s = 0; s < 8; s++) {
        float t;
        if (fine) t = __ldg(&g_zfine[(size_t)ray * NI + sbase + s]);
        else      t = 2.25f + ((float)(sbase + s) + 0.5f) * STEPF;
        const float cxx = 2.0f * fmaf(t, dx, ox);
        const float cyy = 2.0f * fmaf(t, dy, oy);
        const float czz = 2.0f * fmaf(t, dz, oz);
        float feat = 0.0f;
        #pragma unroll
        for (int p = 0; p < 3; p++) {
            const float gx = (p == 2) ? czz : cxx;
            const float gy = (p == 0) ? cyy : ((p == 1) ? czz : cxx);
            const float x = fmaf(gx + 1.0f, 128.0f, -0.5f);
            const float y = fmaf(gy + 1.0f, 128.0f, -0.5f);
            const float x0f = floorf(x), y0f = floorf(y);
            const float wx = x - x0f, wy = y - y0f;
            const int x0 = (int)x0f, y0 = (int)y0f;
            // clamp to [-1,256]; out-of-range hits the zero border
            const int x0c = min(max(x0,     -1), 256);
            const int x1c = min(max(x0 + 1, -1), 256);
            const int y0c = min(max(y0,     -1), 256);
            const int y1c = min(max(y0 + 1, -1), 256);
            const float* base = pb + (size_t)p * PLSZ;
            const int r0 = y0c * HPAD, r1 = y1c * HPAD;
            const float v00 = __ldg(base + (r0 + x0c) * NCH);
            const float v10 = __ldg(base + (r0 + x1c) * NCH);
            const float v01 = __ldg(base + (r1 + x0c) * NCH);
            const float v11 = __ldg(base + (r1 + x1c) * NCH);
            const float iwx = 1.0f - wx, iwy = 1.0f - wy;
            feat += (v00 * iwx + v10 * wx) * iwy + (v01 * iwx + v11 * wx) * wy;
        }
        ff[s] = feat * (1.0f / 3.0f);
    }
    *(float4*)(stg + lane * 12)     = make_float4(ff[0], ff[1], ff[2], ff[3]);
    *(float4*)(stg + lane * 12 + 4) = make_float4(ff[4], ff[5], ff[6], ff[7]);
    __syncwarp();

    // --- hidden layer: lane owns units (2*lane, 2*lane+1), 8 samples ---
    float2 acc[8];
    {
        const float2 bp = sb1p[lane];
        #pragma unroll
        for (int s = 0; s < 8; s++) acc[s] = bp;
    }
    #pragma unroll 4
    for (int c = 0; c < 32; c++) {
        const float4 f03 = *(const float4*)(stg + c * 12);
        const float4 f47 = *(const float4*)(stg + c * 12 + 4);
        const float2 w = sw1p[c * 32 + lane];
        acc[0] = ffma2(make_float2(f03.x, f03.x), w, acc[0]);
        acc[1] = ffma2(make_float2(f03.y, f03.y), w, acc[1]);
        acc[2] = ffma2(make_float2(f03.z, f03.z), w, acc[2]);
        acc[3] = ffma2(make_float2(f03.w, f03.w), w, acc[3]);
        acc[4] = ffma2(make_float2(f47.x, f47.x), w, acc[4]);
        acc[5] = ffma2(make_float2(f47.y, f47.y), w, acc[5]);
        acc[6] = ffma2(make_float2(f47.z, f47.z), w, acc[6]);
        acc[7] = ffma2(make_float2(f47.w, f47.w), w, acc[7]);
    }
    float h0[8], h1[8];
    #pragma unroll
    for (int s = 0; s < 8; s++) {
        h0[s] = softplusf_fast(acc[s].x);
        h1[s] = softplusf_fast(acc[s].y);
    }

    // --- sigma partials + butterfly (8 independent sums) ---
    float p[8];
    {
        const float2 ws = wsig2[lane];
        #pragma unroll
        for (int s = 0; s < 8; s++) p[s] = fmaf(h0[s], ws.x, h1[s] * ws.y);
    }
    #pragma unroll
    for (int off = 16; off; off >>= 1) {
        #pragma unroll
        for (int s = 0; s < 8; s++)
            p[s] += __shfl_xor_sync(0xffffffffu, p[s], off);
    }

    __syncwarp();
    *(float4*)(stg + lane * 36 + 0)  = make_float4(h0[0], h1[0], h0[1], h1[1]);
    *(float4*)(stg + lane * 36 + 4)  = make_float4(h0[2], h1[2], h0[3], h1[3]);
    *(float4*)(stg + lane * 36 + 8)  = make_float4(h0[4], h1[4], h0[5], h1[5]);
    *(float4*)(stg + lane * 36 + 12) = make_float4(h0[6], h1[6], h0[7], h1[7]);
    __syncwarp();

    // --- output layer: lane = rgb channel, 8 samples ---
    float2 o2[8];
    #pragma unroll
    for (int s = 0; s < 8; s++) o2[s] = make_float2(0.0f, 0.0f);
    #pragma unroll 4
    for (int k = 0; k < 32; k++) {
        const float2 w = sw2p[k * 32 + lane];
        const float4 q0 = *(const float4*)(stg + k * 36 + 0);
        const float4 q1 = *(const float4*)(stg + k * 36 + 4);
        const float4 q2 = *(const float4*)(stg + k * 36 + 8);
        const float4 q3 = *(const float4*)(stg + k * 36 + 12);
        o2[0] = ffma2(make_float2(q0.x, q0.y), w, o2[0]);
        o2[1] = ffma2(make_float2(q0.z, q0.w), w, o2[1]);
        o2[2] = ffma2(make_float2(q1.x, q1.y), w, o2[2]);
        o2[3] = ffma2(make_float2(q1.z, q1.w), w, o2[3]);
        o2[4] = ffma2(make_float2(q2.x, q2.y), w, o2[4]);
        o2[5] = ffma2(make_float2(q2.z, q2.w), w, o2[5]);
        o2[6] = ffma2(make_float2(q3.x, q3.y), w, o2[6]);
        o2[7] = ffma2(make_float2(q3.z, q3.w), w, o2[7]);
    }

    // --- writeback ---
    const float bb = sb2r[lane];
    float* grow = g_rgbb + ((size_t)ray * NALL + soff + sbase) * NCH + lane;
    #pragma unroll
    for (int s = 0; s < 8; s++)
        grow[s * NCH] = sigmoidf_fast(o2[s].x + o2[s].y + bb) * 1.002f - 0.001f;

    float myp = p[0];
    if (lane == 1) myp = p[1];
    if (lane == 2) myp = p[2];
    if (lane == 3) myp = p[3];
    if (lane == 4) myp = p[4];
    if (lane == 5) myp = p[5];
    if (lane == 6) myp = p[6];
    if (lane == 7) myp = p[7];
    if (lane < 8)
        g_sigma[(size_t)ray * NALL + soff + sbase + lane] = myp + sb2sig;
}

// ---------------------------------------------------------------------------
// March: coarse weights -> smoothed pdf/cdf -> 48 fine depths. 1 warp/ray.
// ---------------------------------------------------------------------------
__global__ __launch_bounds__(128) void march_kernel() {
    __shared__ float salpha[4][47];
    __shared__ float swk[4][45];
    __shared__ float scdf[4][46];

    const int warp = threadIdx.x >> 5;
    const int lane = threadIdx.x & 31;
    const int ray  = blockIdx.x * 4 + warp;

    const float* sg = g_sigma + (size_t)ray * NALL;
    for (int i = lane; i < 47; i += 32) {
        const float dens = softplusf_fast(0.5f * (__ldg(sg + i) + __ldg(sg + i + 1)) - 1.0f);
        salpha[warp][i] = 1.0f - __expf(-dens * STEPF);
    }
    __syncwarp();

    if (lane == 0) {
        float wcl[47];
        float T = 1.0f;
        #pragma unroll 4
        for (int i = 0; i < 47; i++) {
            const float a = salpha[warp][i];
            wcl[i] = a * T;
            T *= (1.0f - a + 1e-10f);
        }
        float s = 0.0f;
        #pragma unroll 4
        for (int k = 0; k < 45; k++) {
            const float a  = fmaxf(wcl[k],     wcl[k + 1]) + 0.01f;
            const float bb = fmaxf(wcl[k + 1], wcl[k + 2]) + 0.01f;
            const float v  = 0.5f * (a + bb) + 0.01f + 1e-5f;
            swk[warp][k] = v;
            s += v;
        }
        const float inv = 1.0f / s;
        scdf[warp][0] = 0.0f;
        float acc = 0.0f;
        #pragma unroll 4
        for (int k = 0; k < 45; k++) { acc += swk[warp][k] * inv; scdf[warp][k + 1] = acc; }
    }
    __syncwarp();

    for (int i = lane; i < NI; i += 32) {
        const float u = ((float)i + 0.5f) * (1.0f / 48.0f);
        int idx = 0;
        while (idx < 46 && scdf[warp][idx] <= u) idx++;
        int below = idx - 1; if (below < 0) below = 0; if (below > 45) below = 45;
        int above = idx;     if (above > 45) above = 45;
        const float cb = scdf[warp][below], ca = scdf[warp][above];
        float den = ca - cb; if (den < 1e-5f) den = 1.0f;
        const float bbv = 2.25f + ((float)below + 1.0f) * STEPF;
        const float bav = 2.25f + ((float)above + 1.0f) * STEPF;
        g_zfine[(size_t)ray * NI + i] = fmaf((u - cb) / den, bav - bbv, bbv);
    }
}

// ---------------------------------------------------------------------------
// Final: merge, march, bg MLP, composite. 1 warp/ray.
// ---------------------------------------------------------------------------
__global__ __launch_bounds__(128) void final_kernel(
    const float* __restrict__ rd, const float* __restrict__ zbg,
    const float* __restrict__ bw1, const float* __restrict__ bb1,
    const float* __restrict__ bw2, const float* __restrict__ bb2,
    float* __restrict__ out)
{
    __shared__ float zall[4][NALL];
    __shared__ float sig[4][NALL];
    __shared__ unsigned char perm[4][NALL];
    __shared__ float alpha_s[4][NALL - 1];
    __shared__ float wall[4][NALL - 1];
    __shared__ float bgh[4][64];
    __shared__ float sca[4][3];

    const int warp = threadIdx.x >> 5;
    const int lane = threadIdx.x & 31;
    const int ray  = blockIdx.x * 4 + warp;
    const int b    = ray >> 12;

    const float dx = __ldg(rd + ray * 3 + 0);
    const float dy = __ldg(rd + ray * 3 + 1);
    const float dz = __ldg(rd + ray * 3 + 2);

    for (int i = lane; i < NALL; i += 32) {
        sig[warp][i] = __ldg(&g_sigma[(size_t)ray * NALL + i]);
        zall[warp][i] = (i < SC) ? (2.25f + ((float)i + 0.5f) * STEPF)
                                 : __ldg(&g_zfine[(size_t)ray * NI + i - SC]);
    }

    // --- background MLP (67 -> 64 -> 32) ---
    {
        float a0 = __ldg(bb1 + lane), a1 = __ldg(bb1 + lane + 32);
        a0 = fmaf(dx, __ldg(bw1 + 0 * 64 + lane), a0);
        a1 = fmaf(dx, __ldg(bw1 + 0 * 64 + 32 + lane), a1);
        a0 = fmaf(dy, __ldg(bw1 + 1 * 64 + lane), a0);
        a1 = fmaf(dy, __ldg(bw1 + 1 * 64 + 32 + lane), a1);
        a0 = fmaf(dz, __ldg(bw1 + 2 * 64 + lane), a0);
        a1 = fmaf(dz, __ldg(bw1 + 2 * 64 + 32 + lane), a1);
        const float* zb = zbg + b * 64;
        #pragma unroll 4
        for (int i = 0; i < 64; i++) {
            const float x = __ldg(zb + i);
            a0 = fmaf(x, __ldg(bw1 + (3 + i) * 64 + lane), a0);
            a1 = fmaf(x, __ldg(bw1 + (3 + i) * 64 + 32 + lane), a1);
        }
        bgh[warp][lane]      = softplusf_fast(a0);
        bgh[warp][lane + 32] = softplusf_fast(a1);
    }
    __syncwarp();
    float bgc_r = __ldg(bb2 + lane);
    #pragma unroll 8
    for (int h = 0; h < 64; h++)
        bgc_r = fmaf(bgh[warp][h], __ldg(bw2 + h * 32 + lane), bgc_r);
    bgc_r = sigmoidf_fast(bgc_r);
    __syncwarp();

    // --- stable merge by rank-counting ---
    for (int i = lane; i < SC; i += 32) {
        const float zv = zall[warp][i];
        int c = 0;
        #pragma unroll 8
        for (int k = 0; k < NI; k++) c += (zall[warp][SC + k] < zv) ? 1 : 0;
        perm[warp][i + c] = (unsigned char)i;
    }
    for (int j = lane; j < NI; j += 32) {
        const float zv = zall[warp][SC + j];
        int c = 0;
        #pragma unroll 8
        for (int k = 0; k < SC; k++) c += (zall[warp][k] <= zv) ? 1 : 0;
        perm[warp][j + c] = (unsigned char)(SC + j);
    }
    __syncwarp();

    for (int k = lane; k < NALL - 1; k += 32) {
        const float delta = zall[warp][perm[warp][k + 1]] - zall[warp][perm[warp][k]];
        const float dens  = softplusf_fast(0.5f * (sig[warp][perm[warp][k]] +
                                                   sig[warp][perm[warp][k + 1]]) - 1.0f);
        alpha_s[warp][k] = 1.0f - __expf(-dens * delta);
    }
    __syncwarp();

    if (lane == 0) {
        float T = 1.0f, wt = 0.0f, dacc = 0.0f;
        float dprev = zall[warp][perm[warp][0]];
        #pragma unroll 4
        for (int k = 0; k < NALL - 1; k++) {
            const float dnext = zall[warp][perm[warp][k + 1]];
            const float a = alpha_s[warp][k];
            const float w = a * T;
            wall[warp][k] = w;
            wt += w;
            dacc = fmaf(w, 0.5f * (dprev + dnext), dacc);
            T *= (1.0f - a + 1e-10f);
            dprev = dnext;
        }
        sca[warp][0] = T; sca[warp][1] = wt; sca[warp][2] = dacc;
    }
    __syncwarp();

    const size_t rbase = (size_t)ray * NALL * NCH + lane;
    float rprev = __ldg(&g_rgbb[rbase + (size_t)perm[warp][0] * NCH]);
    float acc = 0.0f;
    #pragma unroll 5
    for (int k = 0; k < NALL - 1; k++) {
        const float rnext = __ldg(&g_rgbb[rbase + (size_t)perm[warp][k + 1] * NCH]);
        acc = fmaf(wall[warp][k], 0.5f * (rprev + rnext), acc);
        rprev = rnext;
    }
    acc = fmaf(sca[warp][0], bgc_r, acc);

    float* out_rgb   = out;
    float* out_depth = out + (size_t)NR * 32;
    float* out_wsum  = out + (size_t)NR * 33;

    out_rgb[(size_t)ray * 32 + lane] = acc * 2.0f - 1.0f;
    if (lane == 0) {
        float dv = sca[warp][2] / sca[warp][1];
        if (dv != dv) dv = INFINITY;
        const float ZMIN = 2.25f + 0.5f  * STEPF;
        const float ZMAX = 2.25f + 47.5f * STEPF;
        dv = fminf(fmaxf(dv, ZMIN), ZMAX);
        out_depth[ray] = dv;
        out_wsum[ray]  = sca[warp][1];
    }
}

// ---------------------------------------------------------------------------
extern "C" void kernel_launch(void* const* d_in, const int* in_sizes, int n_in,
                              void* d_out, int out_size) {
    const float* planes = (const float*)d_in[0];
    const float* ro     = (const float*)d_in[1];
    const float* rd     = (const float*)d_in[2];
    const float* zbg    = (const float*)d_in[3];
    const float* w1     = (const float*)d_in[4];
    const float* b1     = (const float*)d_in[5];
    const float* w2     = (const float*)d_in[6];
    const float* b2     = (const float*)d_in[7];
    const float* bw1    = (const float*)d_in[8];
    const float* bb1    = (const float*)d_in[9];
    const float* bw2    = (const float*)d_in[10];
    const float* bb2    = (const float*)d_in[11];
    float* out = (float*)d_out;

    pack_weights_kernel<<<1, 128>>>(w1, b1, w2, b2);
    dim3 tgrid(HRES * HRES / 32, BATCH * 3);
    transpose_planes_kernel<<<tgrid, dim3(32, 8)>>>(planes);

    const int decode_blocks = NR * 6 / 4;
    decode_kernel<<<decode_blocks, 128>>>(ro, rd, w1, 0);
    march_kernel<<<NR / 4, 128>>>();
    decode_kernel<<<decode_blocks, 128>>>(ro, rd, w1, 1);
    final_kernel<<<NR / 4, 128>>>(rd, zbg, bw1, bb1, bw2, bb2, out);
}

// round 10
// speedup vs baseline: 11.2520x; 1.0363x over previous
#include <cuda_runtime.h>
#include <math.h>

#define BATCH 4
#define RAYS  4096
#define NR    (BATCH * RAYS)
#define NCH   32
#define HRES  256
#define HPAD  258
#define PLSZ  (HPAD * HPAD * NCH)
#define SC    48
#define NI    48
#define NALL  96
#define STEPF ((3.3f - 2.25f) / 47.0f)

// Bordered transposed planes: (B,3,258,258,C); 1-px border stays zero.
__device__ float g_planesT[(size_t)BATCH * 3 * PLSZ];
__device__ float g_sigma[(size_t)NR * NALL];
__device__ float g_rgbb[(size_t)NR * NALL * NCH];
__device__ float g_zfine[(size_t)NR * NI];
// Packed decode weights: [0..511] f4 = w2p pairs, [512..527] f4 = wsig2,
// [528..543] f4 = b1 pairs, floats 2176..2207 = b2[1..32], 2208 = b2[0].
__device__ float4 g_wpack[560];

__device__ __forceinline__ float softplusf_fast(float x) {
    return fmaxf(x, 0.0f) + __logf(1.0f + __expf(-fabsf(x)));
}
__device__ __forceinline__ float sigmoidf_fast(float x) {
    return 1.0f / (1.0f + __expf(-x));
}
__device__ __forceinline__ float2 ffma2(float2 a, float2 b, float2 c) {
    unsigned long long ra = *reinterpret_cast<unsigned long long*>(&a);
    unsigned long long rb = *reinterpret_cast<unsigned long long*>(&b);
    unsigned long long rc = *reinterpret_cast<unsigned long long*>(&c);
    unsigned long long rd;
    asm("fma.rn.f32x2 %0, %1, %2, %3;" : "=l"(rd) : "l"(ra), "l"(rb), "l"(rc));
    return *reinterpret_cast<float2*>(&rd);
}

// ---------------------------------------------------------------------------
// Pack decode weights once.
// ---------------------------------------------------------------------------
__global__ void pack_weights_kernel(const float* __restrict__ w1,
                                    const float* __restrict__ b1,
                                    const float* __restrict__ w2,
                                    const float* __restrict__ b2) {
    const int tid = threadIdx.x;
    float2* wp2 = (float2*)g_wpack;
    float*  wpf = (float*)g_wpack;
    for (int i = tid; i < 1024; i += 128) {
        const int k = i >> 5, ch = i & 31;
        wp2[i] = make_float2(w2[(2 * k) * 33 + 1 + ch], w2[(2 * k + 1) * 33 + 1 + ch]);
    }
    if (tid < 32) {
        wp2[1024 + tid] = make_float2(w2[(2 * tid) * 33], w2[(2 * tid + 1) * 33]);
        wp2[1056 + tid] = ((const float2*)b1)[tid];
        wpf[2176 + tid] = b2[1 + tid];
    }
    if (tid == 0) wpf[2208] = b2[0];
    (void)w1;
}

// ---------------------------------------------------------------------------
// Transpose (B,3,C,256,256) -> bordered (B,3,258,258,C)
// ---------------------------------------------------------------------------
__global__ void transpose_planes_kernel(const float* __restrict__ planes) {
    __shared__ float tile[32][33];
    const int bp  = blockIdx.y;
    const int hw0 = blockIdx.x * 32;
    const float* src = planes + (size_t)bp * NCH * HRES * HRES;
    #pragma unroll
    for (int c = threadIdx.y; c < 32; c += 8)
        tile[c][threadIdx.x] = src[(size_t)c * (HRES * HRES) + hw0 + threadIdx.x];
    __syncthreads();
    float* dst = g_planesT + (size_t)bp * PLSZ;
    #pragma unroll
    for (int r = threadIdx.y; r < 32; r += 8) {
        const int hw = hw0 + r;
        const int y = hw >> 8, x = hw & 255;
        dst[(size_t)((y + 1) * HPAD + (x + 1)) * NCH + threadIdx.x] = tile[threadIdx.x][r];
    }
}

// ---------------------------------------------------------------------------
// Decode: sample-parallel warp-GEMM. 1 warp = 8 samples of one ray.
// ---------------------------------------------------------------------------
__global__ __launch_bounds__(128, 6) void decode_kernel(
    const float* __restrict__ ro, const float* __restrict__ rd,
    const float* __restrict__ w1, const int fine)
{
    __shared__ __align__(16) float2 sw1p[32 * 32];
    __shared__ __align__(16) float2 sw2p[32 * 32];
    __shared__ __align__(16) float2 wsig2[32];
    __shared__ __align__(16) float2 sb1p[32];
    __shared__ float  sb2r[32];
    __shared__ float  sb2sig;
    __shared__ __align__(16) float sstage[4][1152];

    const int tid  = threadIdx.x;
    const int warp = tid >> 5;
    const int lane = tid & 31;

    {   // stage weights: contiguous float4 copies
        const float4* w1v4 = (const float4*)w1;
        float4* d1 = (float4*)sw1p;
        #pragma unroll
        for (int i = tid; i < 512; i += 128) d1[i] = w1v4[i];
        float4* d2 = (float4*)sw2p;
        #pragma unroll
        for (int i = tid; i < 512; i += 128) d2[i] = g_wpack[i];
        if (tid < 16) {
            ((float4*)wsig2)[tid] = g_wpack[512 + tid];
            ((float4*)sb1p)[tid]  = g_wpack[528 + tid];
        }
        const float* wpf = (const float*)g_wpack;
        if (tid < 32) sb2r[tid] = wpf[2176 + tid];
        if (tid == 0) sb2sig = wpf[2208];
    }
    __syncthreads();

    const int gw    = blockIdx.x * 4 + warp;
    const int ray   = gw / 6;
    const int sbase = (gw % 6) * 8;
    const int b     = ray >> 12;
    const int soff  = fine ? SC : 0;

    const float ox = __ldg(ro + ray * 3 + 0);
    const float oy = __ldg(ro + ray * 3 + 1);
    const float oz = __ldg(ro + ray * 3 + 2);
    const float dx = __ldg(rd + ray * 3 + 0);
    const float dy = __ldg(rd + ray * 3 + 1);
    const float dz = __ldg(rd + ray * 3 + 2);

    // premultiplied pixel-space ray constants: x_px = t*a + b
    const float axc = 256.0f * dx, bxc = fmaf(256.0f, ox, 127.5f);
    const float ayc = 256.0f * dy, byc = fmaf(256.0f, oy, 127.5f);
    const float azc = 256.0f * dz, bzc = fmaf(256.0f, oz, 127.5f);

    const float* pb = g_planesT + (size_t)(b * 3) * PLSZ + (HPAD + 1) * NCH + lane;
    float* stg = sstage[warp];

    // --- gather 8 samples (lane = channel; zero-border taps) ---
    float ff[8];
    #pragma unroll
    for (int s = 0; s < 8; s++) {
        float t;
        if (fine) t = __ldg(&g_zfine[(size_t)ray * NI + sbase + s]);
        else      t = 2.25f + ((float)(sbase + s) + 0.5f) * STEPF;
        const float X = fmaf(t, axc, bxc);
        const float Y = fmaf(t, ayc, byc);
        const float Z = fmaf(t, azc, bzc);
        float feat = 0.0f;
        #pragma unroll
        for (int p = 0; p < 3; p++) {
            const float x = (p == 2) ? Z : X;
            const float y = (p == 0) ? Y : ((p == 1) ? Z : X);
            const float x0f = floorf(x), y0f = floorf(y);
            const float wx = x - x0f, wy = y - y0f;
            const int x0 = (int)x0f, y0 = (int)y0f;
            const int x0c = min(max(x0,     -1), 256);
            const int x1c = min(max(x0 + 1, -1), 256);
            const int y0c = min(max(y0,     -1), 256);
            const int y1c = min(max(y0 + 1, -1), 256);
            const float* base = pb + (size_t)p * PLSZ;
            const int r0 = y0c * HPAD, r1 = y1c * HPAD;
            const float v00 = __ldg(base + (r0 + x0c) * NCH);
            const float v10 = __ldg(base + (r0 + x1c) * NCH);
            const float v01 = __ldg(base + (r1 + x0c) * NCH);
            const float v11 = __ldg(base + (r1 + x1c) * NCH);
            const float iwx = 1.0f - wx, iwy = 1.0f - wy;
            feat += (v00 * iwx + v10 * wx) * iwy + (v01 * iwx + v11 * wx) * wy;
        }
        ff[s] = feat * (1.0f / 3.0f);
    }
    *(float4*)(stg + lane * 12)     = make_float4(ff[0], ff[1], ff[2], ff[3]);
    *(float4*)(stg + lane * 12 + 4) = make_float4(ff[4], ff[5], ff[6], ff[7]);
    __syncwarp();

    // --- hidden layer ---
    float2 acc[8];
    {
        const float2 bp = sb1p[lane];
        #pragma unroll
        for (int s = 0; s < 8; s++) acc[s] = bp;
    }
    #pragma unroll 4
    for (int c = 0; c < 32; c++) {
        const float4 f03 = *(const float4*)(stg + c * 12);
        const float4 f47 = *(const float4*)(stg + c * 12 + 4);
        const float2 w = sw1p[c * 32 + lane];
        acc[0] = ffma2(make_float2(f03.x, f03.x), w, acc[0]);
        acc[1] = ffma2(make_float2(f03.y, f03.y), w, acc[1]);
        acc[2] = ffma2(make_float2(f03.z, f03.z), w, acc[2]);
        acc[3] = ffma2(make_float2(f03.w, f03.w), w, acc[3]);
        acc[4] = ffma2(make_float2(f47.x, f47.x), w, acc[4]);
        acc[5] = ffma2(make_float2(f47.y, f47.y), w, acc[5]);
        acc[6] = ffma2(make_float2(f47.z, f47.z), w, acc[6]);
        acc[7] = ffma2(make_float2(f47.w, f47.w), w, acc[7]);
    }
    float h0[8], h1[8];
    #pragma unroll
    for (int s = 0; s < 8; s++) {
        h0[s] = softplusf_fast(acc[s].x);
        h1[s] = softplusf_fast(acc[s].y);
    }

    // --- sigma partials + butterfly ---
    float p[8];
    {
        const float2 ws = wsig2[lane];
        #pragma unroll
        for (int s = 0; s < 8; s++) p[s] = fmaf(h0[s], ws.x, h1[s] * ws.y);
    }
    #pragma unroll
    for (int off = 16; off; off >>= 1) {
        #pragma unroll
        for (int s = 0; s < 8; s++)
            p[s] += __shfl_xor_sync(0xffffffffu, p[s], off);
    }

    __syncwarp();
    *(float4*)(stg + lane * 36 + 0)  = make_float4(h0[0], h1[0], h0[1], h1[1]);
    *(float4*)(stg + lane * 36 + 4)  = make_float4(h0[2], h1[2], h0[3], h1[3]);
    *(float4*)(stg + lane * 36 + 8)  = make_float4(h0[4], h1[4], h0[5], h1[5]);
    *(float4*)(stg + lane * 36 + 12) = make_float4(h0[6], h1[6], h0[7], h1[7]);
    __syncwarp();

    // --- output layer ---
    float2 o2[8];
    #pragma unroll
    for (int s = 0; s < 8; s++) o2[s] = make_float2(0.0f, 0.0f);
    #pragma unroll 4
    for (int k = 0; k < 32; k++) {
        const float2 w = sw2p[k * 32 + lane];
        const float4 q0 = *(const float4*)(stg + k * 36 + 0);
        const float4 q1 = *(const float4*)(stg + k * 36 + 4);
        const float4 q2 = *(const float4*)(stg + k * 36 + 8);
        const float4 q3 = *(const float4*)(stg + k * 36 + 12);
        o2[0] = ffma2(make_float2(q0.x, q0.y), w, o2[0]);
        o2[1] = ffma2(make_float2(q0.z, q0.w), w, o2[1]);
        o2[2] = ffma2(make_float2(q1.x, q1.y), w, o2[2]);
        o2[3] = ffma2(make_float2(q1.z, q1.w), w, o2[3]);
        o2[4] = ffma2(make_float2(q2.x, q2.y), w, o2[4]);
        o2[5] = ffma2(make_float2(q2.z, q2.w), w, o2[5]);
        o2[6] = ffma2(make_float2(q3.x, q3.y), w, o2[6]);
        o2[7] = ffma2(make_float2(q3.z, q3.w), w, o2[7]);
    }

    const float bb = sb2r[lane];
    float* grow = g_rgbb + ((size_t)ray * NALL + soff + sbase) * NCH + lane;
    #pragma unroll
    for (int s = 0; s < 8; s++)
        grow[s * NCH] = sigmoidf_fast(o2[s].x + o2[s].y + bb) * 1.002f - 0.001f;

    float myp = p[0];
    if (lane == 1) myp = p[1];
    if (lane == 2) myp = p[2];
    if (lane == 3) myp = p[3];
    if (lane == 4) myp = p[4];
    if (lane == 5) myp = p[5];
    if (lane == 6) myp = p[6];
    if (lane == 7) myp = p[7];
    if (lane < 8)
        g_sigma[(size_t)ray * NALL + soff + sbase + lane] = myp + sb2sig;
}

// ---------------------------------------------------------------------------
// March: warp-parallel predicated scans (no serial lane-0 chains).
// ---------------------------------------------------------------------------
__global__ __launch_bounds__(128) void march_kernel() {
    __shared__ float salpha[4][47];
    __shared__ float swcl[4][47];
    __shared__ float swk[4][45];
    __shared__ float scdf[4][46];

    const int warp = threadIdx.x >> 5;
    const int lane = threadIdx.x & 31;
    const int ray  = blockIdx.x * 4 + warp;

    const float* sg = g_sigma + (size_t)ray * NALL;
    for (int i = lane; i < 47; i += 32) {
        const float dens = softplusf_fast(0.5f * (__ldg(sg + i) + __ldg(sg + i + 1)) - 1.0f);
        salpha[warp][i] = 1.0f - __expf(-dens * STEPF);
    }
    __syncwarp();

    // T_i = prod_{j<i}(1-a_j+eps): predicated scan, idx = lane and lane+32
    {
        float Ta = 1.0f, Tb = 1.0f;
        #pragma unroll 4
        for (int j = 0; j < 46; j++) {
            const float fj = 1.0f - salpha[warp][j] + 1e-10f;
            if (j < lane)      Ta *= fj;
            if (j < lane + 32) Tb *= fj;
        }
        swcl[warp][lane] = salpha[warp][lane] * Ta;
        if (lane + 32 < 47)
            swcl[warp][lane + 32] = salpha[warp][lane + 32] * Tb;
    }
    __syncwarp();

    // smoothed pdf values + total (butterfly)
    float ssum = 0.0f;
    #pragma unroll
    for (int kk = 0; kk < 2; kk++) {
        const int k = lane + kk * 32;
        if (k < 45) {
            const float a  = fmaxf(swcl[warp][k],     swcl[warp][k + 1]) + 0.01f;
            const float bb = fmaxf(swcl[warp][k + 1], swcl[warp][k + 2]) + 0.01f;
            const float v  = 0.5f * (a + bb) + 0.01f + 1e-5f;
            swk[warp][k] = v;
            ssum += v;
        }
    }
    #pragma unroll
    for (int off = 16; off; off >>= 1)
        ssum += __shfl_xor_sync(0xffffffffu, ssum, off);
    const float inv = 1.0f / ssum;
    __syncwarp();

    // cdf prefix (inclusive over swk), predicated scan
    {
        float ca = 0.0f, cb = 0.0f;
        #pragma unroll 4
        for (int j = 0; j < 45; j++) {
            const float vj = swk[warp][j];
            if (j <= lane)      ca += vj;
            if (j <= lane + 32) cb += vj;
        }
        if (lane == 0) scdf[warp][0] = 0.0f;
        scdf[warp][lane + 1] = ca * inv;
        if (lane + 33 <= 45) scdf[warp][lane + 33] = cb * inv;
    }
    __syncwarp();

    for (int i = lane; i < NI; i += 32) {
        const float u = ((float)i + 0.5f) * (1.0f / 48.0f);
        int idx = 0;
        while (idx < 46 && scdf[warp][idx] <= u) idx++;
        int below = idx - 1; if (below < 0) below = 0; if (below > 45) below = 45;
        int above = idx;     if (above > 45) above = 45;
        const float cb = scdf[warp][below], ca = scdf[warp][above];
        float den = ca - cb; if (den < 1e-5f) den = 1.0f;
        const float bbv = 2.25f + ((float)below + 1.0f) * STEPF;
        const float bav = 2.25f + ((float)above + 1.0f) * STEPF;
        g_zfine[(size_t)ray * NI + i] = fmaf((u - cb) / den, bav - bbv, bbv);
    }
}

// ---------------------------------------------------------------------------
// Final: merge + parallel-scan march + bg MLP + composite. 1 warp/ray.
// ---------------------------------------------------------------------------
__global__ __launch_bounds__(128) void final_kernel(
    const float* __restrict__ rd, const float* __restrict__ zbg,
    const float* __restrict__ bw1, const float* __restrict__ bb1,
    const float* __restrict__ bw2, const float* __restrict__ bb2,
    float* __restrict__ out)
{
    __shared__ float zall[4][NALL];
    __shared__ float sig[4][NALL];
    __shared__ unsigned char perm[4][NALL];
    __shared__ float alpha_s[4][NALL - 1];
    __shared__ float wall[4][NALL - 1];
    __shared__ float bgh[4][64];

    const int warp = threadIdx.x >> 5;
    const int lane = threadIdx.x & 31;
    const int ray  = blockIdx.x * 4 + warp;
    const int b    = ray >> 12;

    const float dx = __ldg(rd + ray * 3 + 0);
    const float dy = __ldg(rd + ray * 3 + 1);
    const float dz = __ldg(rd + ray * 3 + 2);

    for (int i = lane; i < NALL; i += 32) {
        sig[warp][i] = __ldg(&g_sigma[(size_t)ray * NALL + i]);
        zall[warp][i] = (i < SC) ? (2.25f + ((float)i + 0.5f) * STEPF)
                                 : __ldg(&g_zfine[(size_t)ray * NI + i - SC]);
    }

    // --- background MLP (67 -> 64 -> 32) ---
    {
        float a0 = __ldg(bb1 + lane), a1 = __ldg(bb1 + lane + 32);
        a0 = fmaf(dx, __ldg(bw1 + 0 * 64 + lane), a0);
        a1 = fmaf(dx, __ldg(bw1 + 0 * 64 + 32 + lane), a1);
        a0 = fmaf(dy, __ldg(bw1 + 1 * 64 + lane), a0);
        a1 = fmaf(dy, __ldg(bw1 + 1 * 64 + 32 + lane), a1);
        a0 = fmaf(dz, __ldg(bw1 + 2 * 64 + lane), a0);
        a1 = fmaf(dz, __ldg(bw1 + 2 * 64 + 32 + lane), a1);
        const float* zb = zbg + b * 64;
        #pragma unroll 4
        for (int i = 0; i < 64; i++) {
            const float x = __ldg(zb + i);
            a0 = fmaf(x, __ldg(bw1 + (3 + i) * 64 + lane), a0);
            a1 = fmaf(x, __ldg(bw1 + (3 + i) * 64 + 32 + lane), a1);
        }
        bgh[warp][lane]      = softplusf_fast(a0);
        bgh[warp][lane + 32] = softplusf_fast(a1);
    }
    __syncwarp();
    float bgc_r = __ldg(bb2 + lane);
    #pragma unroll 8
    for (int h = 0; h < 64; h++)
        bgc_r = fmaf(bgh[warp][h], __ldg(bw2 + h * 32 + lane), bgc_r);
    bgc_r = sigmoidf_fast(bgc_r);
    __syncwarp();

    // --- stable merge by rank-counting ---
    for (int i = lane; i < SC; i += 32) {
        const float zv = zall[warp][i];
        int c = 0;
        #pragma unroll 8
        for (int k = 0; k < NI; k++) c += (zall[warp][SC + k] < zv) ? 1 : 0;
        perm[warp][i + c] = (unsigned char)i;
    }
    for (int j = lane; j < NI; j += 32) {
        const float zv = zall[warp][SC + j];
        int c = 0;
        #pragma unroll 8
        for (int k = 0; k < SC; k++) c += (zall[warp][k] <= zv) ? 1 : 0;
        perm[warp][j + c] = (unsigned char)(SC + j);
    }
    __syncwarp();

    for (int k = lane; k < NALL - 1; k += 32) {
        const float delta = zall[warp][perm[warp][k + 1]] - zall[warp][perm[warp][k]];
        const float dens  = softplusf_fast(0.5f * (sig[warp][perm[warp][k]] +
                                                   sig[warp][perm[warp][k + 1]]) - 1.0f);
        alpha_s[warp][k] = 1.0f - __expf(-dens * delta);
    }
    __syncwarp();

    // --- transmittance: predicated product scan over 95 factors ---
    float T0 = 1.0f, T1 = 1.0f, T2 = 1.0f, Tall = 1.0f;
    #pragma unroll 4
    for (int j = 0; j < NALL - 1; j++) {
        const float fj = 1.0f - alpha_s[warp][j] + 1e-10f;
        if (j < lane)      T0 *= fj;
        if (j < lane + 32) T1 *= fj;
        if (j < lane + 64) T2 *= fj;
        Tall *= fj;
    }
    float wt = 0.0f, dacc = 0.0f;
    {
        const int k = lane;   // k in [0,31]
        const float w = alpha_s[warp][k] * T0;
        wall[warp][k] = w;
        wt += w;
        dacc = fmaf(w, 0.5f * (zall[warp][perm[warp][k]] + zall[warp][perm[warp][k + 1]]), dacc);
    }
    {
        const int k = lane + 32;   // [32,63]
        const float w = alpha_s[warp][k] * T1;
        wall[warp][k] = w;
        wt += w;
        dacc = fmaf(w, 0.5f * (zall[warp][perm[warp][k]] + zall[warp][perm[warp][k + 1]]), dacc);
    }
    if (lane + 64 < NALL - 1) {    // [64,94]
        const int k = lane + 64;
        const float w = alpha_s[warp][k] * T2;
        wall[warp][k] = w;
        wt += w;
        dacc = fmaf(w, 0.5f * (zall[warp][perm[warp][k]] + zall[warp][perm[warp][k + 1]]), dacc);
    }
    #pragma unroll
    for (int off = 16; off; off >>= 1) {
        wt   += __shfl_xor_sync(0xffffffffu, wt, off);
        dacc += __shfl_xor_sync(0xffffffffu, dacc, off);
    }
    __syncwarp();

    // --- composite (lane = channel) ---
    const size_t rbase = (size_t)ray * NALL * NCH + lane;
    float rprev = __ldg(&g_rgbb[rbase + (size_t)perm[warp][0] * NCH]);
    float acc = 0.0f;
    #pragma unroll 5
    for (int k = 0; k < NALL - 1; k++) {
        const float rnext = __ldg(&g_rgbb[rbase + (size_t)perm[warp][k + 1] * NCH]);
        acc = fmaf(wall[warp][k], 0.5f * (rprev + rnext), acc);
        rprev = rnext;
    }
    acc = fmaf(Tall, bgc_r, acc);

    float* out_rgb   = out;
    float* out_depth = out + (size_t)NR * 32;
    float* out_wsum  = out + (size_t)NR * 33;

    out_rgb[(size_t)ray * 32 + lane] = acc * 2.0f - 1.0f;
    if (lane == 0) {
        float dv = dacc / wt;
        if (dv != dv) dv = INFINITY;
        const float ZMIN = 2.25f + 0.5f  * STEPF;
        const float ZMAX = 2.25f + 47.5f * STEPF;
        dv = fminf(fmaxf(dv, ZMIN), ZMAX);
        out_depth[ray] = dv;
        out_wsum[ray]  = wt;
    }
}

// ---------------------------------------------------------------------------
extern "C" void kernel_launch(void* const* d_in, const int* in_sizes, int n_in,
                              void* d_out, int out_size) {
    const float* planes = (const float*)d_in[0];
    const float* ro     = (const float*)d_in[1];
    const float* rd     = (const float*)d_in[2];
    const float* zbg    = (const float*)d_in[3];
    const float* w1     = (const float*)d_in[4];
    const float* b1     = (const float*)d_in[5];
    const float* w2     = (const float*)d_in[6];
    const float* b2     = (const float*)d_in[7];
    const float* bw1    = (const float*)d_in[8];
    const float* bb1    = (const float*)d_in[9];
    const float* bw2    = (const float*)d_in[10];
    const float* bb2    = (const float*)d_in[11];
    float* out = (float*)d_out;

    pack_weights_kernel<<<1, 128>>>(w1, b1, w2, b2);
    dim3 tgrid(HRES * HRES / 32, BATCH * 3);
    transpose_planes_kernel<<<tgrid, dim3(32, 8)>>>(planes);

    const int decode_blocks = NR * 6 / 4;
    decode_kernel<<<decode_blocks, 128>>>(ro, rd, w1, 0);
    march_kernel<<<NR / 4, 128>>>();
    decode_kernel<<<decode_blocks, 128>>>(ro, rd, w1, 1);
    final_kernel<<<NR / 4, 128>>>(rd, zbg, bw1, bb1, bw2, bb2, out);
}